// round 6
// baseline (speedup 1.0000x reference)
#include <cuda_runtime.h>
#include <stdint.h>

#define IN_DIM   4096
#define OUT_DIM  1024
#define RB       64      // x rows per block (2 per lane: L and L+32)
#define KT       512     // K columns per phase
#define NPH      8       // IN_DIM / KT
#define TPB      1024
#define OPW      16      // outputs per warp
#define OSPLIT   2       // output groups
#define OPB      (OUT_DIM / OSPLIT)   // 512 outputs per block
#define NSLICE   (NPH * OSPLIT)       // 16 (phase, outgroup) slices
#define SLICE_CAP 4096   // padded entries per slice (avg ~2816, huge margin)
#define XS_STRIDE 513    // 513 % 32 == 1 -> bank = (row + col) % 32, conflict-free
#define ROW32_BYTES (32 * XS_STRIDE * 4)
#define SMEM_BYTES  (RB * XS_STRIDE * 4 + SLICE_CAP * 8 + (OPB + 1) * 4)  // 166148

// Phase-major packed sparse table (rebuilt every launch; deterministic).
// Slice s = p*OSPLIT + og: entries of phase p for outputs [og*512, og*512+512),
// packed contiguously. Every output's segment is padded to EVEN length with
// null entries (off=0, val=0) so segments are int4 (2-entry) aligned.
// Entry = { byte offset of col within its KT-segment, fp32 value bits }.
__device__ int  g_cnt[NPH * OUT_DIM];         // padded (even) counts
__device__ int  g_soff[NSLICE][OPB + 1];      // exclusive scan of padded counts
__device__ int2 g_ptab[NSLICE * SLICE_CAP];

// ---------------------------------------------------------------------------
// Prep 1: padded nonzero count per (output o, phase q).
// ---------------------------------------------------------------------------
__global__ void __launch_bounds__(256) count_kernel(const float* __restrict__ Phi) {
    const int o = blockIdx.x, t = threadIdx.x, q = t >> 5, u = t & 31;
    const float* row = Phi + (size_t)o * IN_DIM;
    int cnt = 0;
#pragma unroll
    for (int k = 0; k < 16; k++) cnt += (row[q * KT + k * 32 + u] != 0.0f);
#pragma unroll
    for (int d = 16; d; d >>= 1) cnt += __shfl_down_sync(0xffffffffu, cnt, d);
    if (u == 0) g_cnt[q * OUT_DIM + o] = (cnt + 1) & ~1;   // pad to even
}

// ---------------------------------------------------------------------------
// Prep 2: exclusive scan of padded counts within each (phase, outgroup) slice.
// ---------------------------------------------------------------------------
__global__ void __launch_bounds__(OPB) scan_kernel() {
    const int s = blockIdx.x;          // s = p*OSPLIT + og
    const int p = s >> 1, og = s & 1, t = threadIdx.x;
    __shared__ int sh[OPB];
    int c = g_cnt[p * OUT_DIM + og * OPB + t];
    sh[t] = c;
    __syncthreads();
#pragma unroll
    for (int d = 1; d < OPB; d <<= 1) {
        int v = (t >= d) ? sh[t - d] : 0;
        __syncthreads();
        sh[t] += v;
        __syncthreads();
    }
    g_soff[s][t] = min(sh[t] - c, SLICE_CAP);
    if (t == OPB - 1) g_soff[s][OPB] = min(sh[t], SLICE_CAP);
}

// ---------------------------------------------------------------------------
// Prep 3: fill packed table (deterministic lane-k order) + null padding.
// ---------------------------------------------------------------------------
__global__ void __launch_bounds__(256) fill_kernel(const float* __restrict__ Phi) {
    const int o = blockIdx.x, t = threadIdx.x, q = t >> 5, u = t & 31;
    const int og = (o >= OPB) ? 1 : 0;
    const int ol = o - og * OPB;
    const int s  = q * OSPLIT + og;
    const float* row = Phi + (size_t)o * IN_DIM;

    float rv[16];
    int cnt = 0;
#pragma unroll
    for (int k = 0; k < 16; k++) { rv[k] = row[q * KT + k * 32 + u]; cnt += (rv[k] != 0.0f); }

    int ex = cnt;
#pragma unroll
    for (int d = 1; d < 32; d <<= 1) {
        int v = __shfl_up_sync(0xffffffffu, ex, d);
        if (u >= d) ex += v;
    }
    int tot = __shfl_sync(0xffffffffu, ex, 31);   // inclusive total at lane 31
    ex -= cnt;                                    // exclusive prefix

    const int base = g_soff[s][ol];
    int dst = base + ex;
#pragma unroll
    for (int k = 0; k < 16; k++) {
        float v = rv[k];
        if (v != 0.0f) {
            if (dst < SLICE_CAP)
                g_ptab[s * SLICE_CAP + dst] = make_int2((k * 32 + u) * 4, __float_as_int(v));
            dst++;
        }
    }
    // pad odd-length segment with one null entry
    if (u == 0 && (tot & 1) && (base + tot) < SLICE_CAP)
        g_ptab[s * SLICE_CAP + base + tot] = make_int2(0, 0);
}

// ---------------------------------------------------------------------------
// Main: sparse out = x @ Phi^T. Block: 64 x-rows (lane L -> rows L, L+32),
// 512 outputs (warp w -> 16 contiguous), 8 K-phases. Hot loop is pure smem:
// 2 entries per LDS.128 (broadcast) -> 4 conflict-free LDS + 4 FFMA.
// ---------------------------------------------------------------------------
__global__ void __launch_bounds__(TPB, 1) spjl_kernel(
    const float* __restrict__ x, float* __restrict__ out, int nrows) {
    extern __shared__ float xs[];                       // x tile [RB * XS_STRIDE]
    int2* st_tab = (int2*)(xs + RB * XS_STRIDE);        // staged slice (16B aligned)
    int*  st_off = (int*)(st_tab + SLICE_CAP);          // staged offsets [OPB+1]

    const int tid = threadIdx.x;
    const int w   = tid >> 5;
    const int L   = tid & 31;
    const int rg  = blockIdx.x >> 1;
    const int og  = blockIdx.x & 1;
    const size_t n0 = (size_t)rg * RB;
    const int olb = w * OPW;                            // warp's first local output

    float acc0[OPW], acc1[OPW];
#pragma unroll
    for (int io = 0; io < OPW; io++) { acc0[io] = 0.0f; acc1[io] = 0.0f; }

    const char* xrow = (const char*)(xs + L * XS_STRIDE);

    for (int p = 0; p < NPH; p++) {
        const int s = p * OSPLIT + og;
        const int len = g_soff[s][OPB];                 // padded total (even)
        __syncthreads();   // previous phase readers done before overwrite

        // Stage x tile: 64 rows x 512 cols (coalesced LDG.64, conflict-free STS).
#pragma unroll
        for (int it = 0; it < (RB * KT / 2) / TPB; it++) {
            int idx2 = tid + it * TPB;
            int rr   = idx2 >> 8;
            int c2   = idx2 & 255;
            size_t gr = n0 + rr;
            float2 v = make_float2(0.0f, 0.0f);
            if (gr < (size_t)nrows)
                v = *(const float2*)(x + gr * IN_DIM + (size_t)p * KT + c2 * 2);
            xs[rr * XS_STRIDE + c2 * 2]     = v.x;
            xs[rr * XS_STRIDE + c2 * 2 + 1] = v.y;
        }
        // Stage table slice (int4 copies) + offsets (coalesced).
        if (tid <= OPB) st_off[tid] = g_soff[s][tid];
        {
            const int4* src = (const int4*)(g_ptab + s * SLICE_CAP);
            int4*       dst = (int4*)st_tab;
            for (int i = tid; i < (len >> 1); i += TPB) dst[i] = src[i];
        }
        __syncthreads();

        int jb = st_off[olb];
#pragma unroll
        for (int io = 0; io < OPW; io++) {
            const int je = st_off[olb + io + 1];
            float a0 = acc0[io], a1 = acc1[io];
            for (int j = jb; j < je; j += 2) {
                int4 e = *(const int4*)(st_tab + j);   // 2 entries, broadcast
                float xv0 = *(const float*)(xrow + e.x);
                float xv1 = *(const float*)(xrow + ROW32_BYTES + e.x);
                a0 = fmaf(__int_as_float(e.y), xv0, a0);
                a1 = fmaf(__int_as_float(e.y), xv1, a1);
                float xw0 = *(const float*)(xrow + e.z);
                float xw1 = *(const float*)(xrow + ROW32_BYTES + e.z);
                a0 = fmaf(__int_as_float(e.w), xw0, a0);
                a1 = fmaf(__int_as_float(e.w), xw1, a1);
            }
            acc0[io] = a0; acc1[io] = a1;
            jb = je;
        }
    }

    __syncthreads();
    // Stage results (alias x tile); bank = (row + col) % 32 -> conflict-free.
#pragma unroll
    for (int io = 0; io < OPW; io++) {
        xs[L * XS_STRIDE        + olb + io] = acc0[io];
        xs[(L + 32) * XS_STRIDE + olb + io] = acc1[io];
    }
    __syncthreads();
    // Coalesced store of 64 rows x 512 outputs.
#pragma unroll
    for (int it = 0; it < (RB * OPB) / TPB; it++) {
        int i  = tid + it * TPB;
        int rr = i >> 9;
        int k  = i & (OPB - 1);
        size_t gr = n0 + rr;
        if (gr < (size_t)nrows)
            out[gr * OUT_DIM + og * OPB + k] = xs[rr * XS_STRIDE + k];
    }
}

extern "C" void kernel_launch(void* const* d_in, const int* in_sizes, int n_in,
                              void* d_out, int out_size) {
    const float* x   = (const float*)d_in[0];   // [N, 4096] fp32
    const float* Phi = (const float*)d_in[1];   // [1024, 4096] fp32
    float* out = (float*)d_out;                 // [N, 1024] fp32

    const int nrows = in_sizes[0] / IN_DIM;              // 16384
    const int grid  = ((nrows + RB - 1) / RB) * OSPLIT;  // 512

    cudaFuncSetAttribute(spjl_kernel,
                         cudaFuncAttributeMaxDynamicSharedMemorySize, SMEM_BYTES);

    count_kernel<<<OUT_DIM, 256>>>(Phi);
    scan_kernel<<<NSLICE, OPB>>>();
    fill_kernel<<<OUT_DIM, 256>>>(Phi);
    spjl_kernel<<<grid, TPB, SMEM_BYTES>>>(x, out, nrows);
}